// round 5
// baseline (speedup 1.0000x reference)
#include <cuda_runtime.h>
#include <cuda_bf16.h>
#include <stdint.h>
#include <math.h>

// ---------------------------------------------------------------------------
// PatchCore pipeline:
//  1) prep: fp32 -> bf16 copies + row squared norms (x2, y2) + g_best init
//  2) approx: bf16 mma.sync GEMM (ldmatrix fragments, 3-stage cp.async
//     pipeline) fused with per-row running min of (y2[m] - 2*dot) packed
//     with index  -> g_best[n]
//  3) cand: per image, top-NCAND patches by approx score
//  4) gemm_exact pass1: fp32 d2 rows for the candidate patches
//  5) rowmin + select: exact argmax patch, exact nn index, exact score
//  6) gemm_exact pass2: fp32 d2 rows for the 16 nn samples
//  7) top9: exact sorted 9 nearest supports
//  8) final: distances, softmax, output
// ---------------------------------------------------------------------------

#define N_EMB 12544
#define M_BANK 16384
#define DIM 1536
#define BSZ 16
#define PPI (N_EMB / BSZ)        // 784
#define NCAND 8
#define NQ1 (BSZ * NCAND)        // 128
#define NSUP 9

#define BMa 256
#define BNa 128
#define BKa 32
#define PK 40                    // padded row stride (bf16) -> LDSM conflict-free
#define NKT (DIM / BKa)          // 48
#define NCHUNK (M_BANK / BNa)    // 128
#define MSPLIT 3
#define NSTAGE 3
#define STAGE_ELEMS ((BMa + BNa) * PK)      // bf16 elems per stage (A then B)

#define APPROX_SMEM (NSTAGE * STAGE_ELEMS * 2 + 256 * 8)        // 94208 B
#define TOP9_SMEM ((M_BANK + 256) * 8)                           // 133120 B

// ------------------------- device scratch (static) -------------------------
__device__ __nv_bfloat16 g_emb_bf[(size_t)N_EMB * DIM];
__device__ __nv_bfloat16 g_mb_bf[(size_t)M_BANK * DIM];
__device__ float g_x2[N_EMB];
__device__ float g_y2[M_BANK];
__device__ unsigned long long g_best[N_EMB];
__device__ int g_cand[NQ1];
__device__ float g_d2q[(size_t)NQ1 * M_BANK];
__device__ unsigned long long g_cpack[NQ1];
__device__ int g_sel_patch[BSZ];
__device__ int g_sel_nn[BSZ];
__device__ float g_sel_score[BSZ];
__device__ int g_support[BSZ * NSUP];

// ------------------------------- helpers -----------------------------------
__device__ __forceinline__ unsigned int fflip(float f) {
    unsigned int u = __float_as_uint(f);
    return (u & 0x80000000u) ? ~u : (u | 0x80000000u);
}
__device__ __forceinline__ float funflip(unsigned int u) {
    u = (u & 0x80000000u) ? (u & 0x7FFFFFFFu) : ~u;
    return __uint_as_float(u);
}
__device__ __forceinline__ unsigned long long packmin(float f, unsigned int idx) {
    return ((unsigned long long)fflip(f) << 32) | (unsigned long long)idx;
}
__device__ __forceinline__ float unpackf(unsigned long long p) {
    return funflip((unsigned int)(p >> 32));
}

__device__ __forceinline__ void cpasync16(uint32_t saddr, const void* gptr) {
    asm volatile("cp.async.cg.shared.global [%0], [%1], 16;\n" :: "r"(saddr), "l"(gptr));
}
__device__ __forceinline__ void cp_commit() {
    asm volatile("cp.async.commit_group;\n" ::: "memory");
}
__device__ __forceinline__ void cp_wait1() {
    asm volatile("cp.async.wait_group 1;\n" ::: "memory");
}
__device__ __forceinline__ void cp_wait0() {
    asm volatile("cp.async.wait_group 0;\n" ::: "memory");
}

__device__ __forceinline__ void ldsm_x4(uint32_t* r, uint32_t addr) {
    asm volatile("ldmatrix.sync.aligned.m8n8.x4.shared.b16 {%0,%1,%2,%3}, [%4];\n"
                 : "=r"(r[0]), "=r"(r[1]), "=r"(r[2]), "=r"(r[3]) : "r"(addr));
}

__device__ __forceinline__ void mma16816(float* c, const uint32_t* a, uint32_t b0, uint32_t b1) {
    asm volatile(
        "mma.sync.aligned.m16n8k16.row.col.f32.bf16.bf16.f32 "
        "{%0,%1,%2,%3}, {%4,%5,%6,%7}, {%8,%9}, {%0,%1,%2,%3};\n"
        : "+f"(c[0]), "+f"(c[1]), "+f"(c[2]), "+f"(c[3])
        : "r"(a[0]), "r"(a[1]), "r"(a[2]), "r"(a[3]), "r"(b0), "r"(b1));
}

// ------------------------------ 1) prep ------------------------------------
// one block per row; fp32->bf16, row norm; emb rows also init g_best
__global__ void __launch_bounds__(128) prep_kernel(const float* __restrict__ emb,
                                                   const float* __restrict__ mb) {
    __shared__ float wred[4];
    int row = blockIdx.x;
    const float* src;
    __nv_bfloat16* dst;
    float* normp;
    if (row < N_EMB) {
        src = emb + (size_t)row * DIM;
        dst = g_emb_bf + (size_t)row * DIM;
        normp = &g_x2[row];
        if (threadIdx.x == 0) g_best[row] = ~0ull;
    } else {
        int r = row - N_EMB;
        src = mb + (size_t)r * DIM;
        dst = g_mb_bf + (size_t)r * DIM;
        normp = &g_y2[r];
    }
    int t = threadIdx.x;
    float ss = 0.f;
    const float4* s4 = (const float4*)src;
#pragma unroll
    for (int i = 0; i < DIM / 4 / 128; i++) {       // 3 iterations
        int c = t + i * 128;
        float4 v = s4[c];
        ss = fmaf(v.x, v.x, ss);
        ss = fmaf(v.y, v.y, ss);
        ss = fmaf(v.z, v.z, ss);
        ss = fmaf(v.w, v.w, ss);
        __nv_bfloat162* d2 = (__nv_bfloat162*)(dst + c * 4);
        d2[0] = __floats2bfloat162_rn(v.x, v.y);
        d2[1] = __floats2bfloat162_rn(v.z, v.w);
    }
#pragma unroll
    for (int s = 16; s > 0; s >>= 1) ss += __shfl_xor_sync(0xFFFFFFFFu, ss, s);
    if ((t & 31) == 0) wred[t >> 5] = ss;
    __syncthreads();
    if (t == 0) *normp = wred[0] + wred[1] + wred[2] + wred[3];
}

// ------------------------- 2) approx bf16 GEMM+min -------------------------
// stage layout: [A(BMa x PK)] at stage*STAGE_ELEMS, [B(BNa x PK)] right after A
__device__ __forceinline__ void load_tiles(int t, int row0, int m0, int stage, int kt,
                                           uint32_t sbase) {
    int k0 = kt * BKa;
    uint32_t abase = sbase + (uint32_t)(stage * STAGE_ELEMS) * 2u;
    uint32_t bbase = abase + (uint32_t)(BMa * PK) * 2u;
#pragma unroll
    for (int i = 0; i < 4; i++) {           // A: 256 rows x 32 k = 1024 x 16B chunks
        int c = t + i * 256;
        int r = c >> 2, cc = c & 3;
        uint32_t d = abase + (uint32_t)(r * PK + cc * 8) * 2u;
        cpasync16(d, g_emb_bf + (size_t)(row0 + r) * DIM + k0 + cc * 8);
    }
#pragma unroll
    for (int i = 0; i < 2; i++) {           // B: 128 rows x 32 k = 512 x 16B chunks
        int c = t + i * 256;
        int r = c >> 2, cc = c & 3;
        uint32_t d = bbase + (uint32_t)(r * PK + cc * 8) * 2u;
        cpasync16(d, g_mb_bf + (size_t)(m0 + r) * DIM + k0 + cc * 8);
    }
}

extern "C" __global__ void __launch_bounds__(256, 1) approx_kernel() {
    extern __shared__ char smem[];
    unsigned long long* rowmin =
        (unsigned long long*)(smem + NSTAGE * STAGE_ELEMS * 2);

    int t = threadIdx.x;
    rowmin[t] = ~0ull;
    __syncthreads();

    int lane = t & 31, wid = t >> 5;
    int wr = wid >> 1, wc = wid & 1;   // 4x2 warps, each a 64x64 tile
    int g = lane >> 2, tq = lane & 3;
    int row0 = blockIdx.x * BMa;

    uint32_t sbase = (uint32_t)__cvta_generic_to_shared(smem);

    // ldmatrix per-thread byte offsets (relative to stage A/B base)
    // A .x4: row = wr*64 + i*16 + (lane&15), col = ((lane>>4)&1)*8  (+ kk)
    uint32_t a_off[4];
#pragma unroll
    for (int i = 0; i < 4; i++)
        a_off[i] = (uint32_t)((wr * 64 + i * 16 + (lane & 15)) * PK +
                              ((lane >> 4) & 1) * 8) * 2u;
    // B .x4: row = wc*64 + j*8 + (lane&7), col = (lane>>3)*8  (covers k 0..31)
    uint32_t b_off[8];
#pragma unroll
    for (int j = 0; j < 8; j++)
        b_off[j] = (uint32_t)((wc * 64 + j * 8 + (lane & 7)) * PK +
                              (lane >> 3) * 8) * 2u;

    unsigned long long slot[8];
#pragma unroll
    for (int i = 0; i < 8; i++) slot[i] = ~0ull;

    for (int chunk = blockIdx.y; chunk < NCHUNK; chunk += MSPLIT) {
        int m0 = chunk * BNa;
        float acc[4][8][4];
#pragma unroll
        for (int i = 0; i < 4; i++)
#pragma unroll
            for (int j = 0; j < 8; j++)
#pragma unroll
                for (int v = 0; v < 4; v++) acc[i][j][v] = 0.f;

        // all reads of previous chunk's stages must complete before refill
        __syncthreads();
        load_tiles(t, row0, m0, 0, 0, sbase);
        cp_commit();
        load_tiles(t, row0, m0, 1, 1, sbase);
        cp_commit();

        for (int kt = 0; kt < NKT; kt++) {
            // stage kt%3 ready after this wait (groups complete in order)
            if (kt + 1 < NKT) cp_wait1(); else cp_wait0();
            // (a) make stage kt%3 visible to all threads
            // (b) all threads done reading stage (kt-1)%3 == (kt+2)%3
            __syncthreads();
            if (kt + 2 < NKT) {
                load_tiles(t, row0, m0, (kt + 2) % NSTAGE, kt + 2, sbase);
                cp_commit();
            }

            int stage = kt % NSTAGE;
            uint32_t abase = sbase + (uint32_t)(stage * STAGE_ELEMS) * 2u;
            uint32_t bbase = abase + (uint32_t)(BMa * PK) * 2u;

            // B fragments: one ldmatrix.x4 per j covers k=0..15 (r0,r1) and
            // k=16..31 (r2,r3)
            uint32_t bf[8][4];
#pragma unroll
            for (int j = 0; j < 8; j++) ldsm_x4(bf[j], bbase + b_off[j]);

#pragma unroll
            for (int kk2 = 0; kk2 < 2; kk2++) {
                uint32_t af[4][4];
#pragma unroll
                for (int i = 0; i < 4; i++)
                    ldsm_x4(af[i], abase + a_off[i] + (uint32_t)(kk2 * 16 * 2));
#pragma unroll
                for (int j = 0; j < 8; j++)
#pragma unroll
                    for (int i = 0; i < 4; i++)
                        mma16816(acc[i][j], af[i], bf[j][kk2 * 2], bf[j][kk2 * 2 + 1]);
            }
        }

        // epilogue: key = y2[m] - 2*dot ; running (key, m) min per owned row
#pragma unroll
        for (int j = 0; j < 8; j++) {
            int m = m0 + wc * 64 + j * 8 + tq * 2;
            float y0 = __ldg(&g_y2[m]);
            float y1 = __ldg(&g_y2[m + 1]);
#pragma unroll
            for (int i = 0; i < 4; i++) {
                unsigned long long p;
                p = packmin(fmaf(-2.f, acc[i][j][0], y0), (unsigned)m);
                if (p < slot[i * 2]) slot[i * 2] = p;
                p = packmin(fmaf(-2.f, acc[i][j][1], y1), (unsigned)(m + 1));
                if (p < slot[i * 2]) slot[i * 2] = p;
                p = packmin(fmaf(-2.f, acc[i][j][2], y0), (unsigned)m);
                if (p < slot[i * 2 + 1]) slot[i * 2 + 1] = p;
                p = packmin(fmaf(-2.f, acc[i][j][3], y1), (unsigned)(m + 1));
                if (p < slot[i * 2 + 1]) slot[i * 2 + 1] = p;
            }
        }
    }

#pragma unroll
    for (int i = 0; i < 4; i++) {
        atomicMin(&rowmin[wr * 64 + i * 16 + g], slot[i * 2]);
        atomicMin(&rowmin[wr * 64 + i * 16 + g + 8], slot[i * 2 + 1]);
    }
    __syncthreads();
    atomicMin(&g_best[row0 + t], rowmin[t]);
}

// -------------------- 3) candidate patches per image -----------------------
__global__ void cand_kernel() {
    __shared__ unsigned long long sarr[PPI];
    __shared__ unsigned long long red[256];
    int b = blockIdx.x, t = threadIdx.x;
    for (int p = t; p < PPI; p += 256) {
        int n = b * PPI + p;
        float sc = g_x2[n] + unpackf(g_best[n]);   // approx d2 score
        sarr[p] = ((unsigned long long)fflip(sc) << 32) |
                  (unsigned long long)(0xFFFFFFFFu - (unsigned)p);
    }
    __syncthreads();
    for (int it = 0; it < NCAND; it++) {
        unsigned long long mx = 0ull;
        for (int p = t; p < PPI; p += 256) mx = (sarr[p] > mx) ? sarr[p] : mx;
        red[t] = mx;
        __syncthreads();
        for (int s = 128; s > 0; s >>= 1) {
            if (t < s && red[t + s] > red[t]) red[t] = red[t + s];
            __syncthreads();
        }
        unsigned long long w = red[0];
        int p = (int)(0xFFFFFFFFu - (unsigned)(w & 0xFFFFFFFFull));
        if (t == 0) {
            g_cand[b * NCAND + it] = b * PPI + p;
            sarr[p] = 0ull;
        }
        __syncthreads();
    }
}

// ---------------- 4/6) exact fp32 d2 rows for query sets -------------------
// pass==1: NQ1 candidate embedding rows ; pass==2: 16 nn memory-bank rows
__global__ void __launch_bounds__(256) gemm_exact(const float* __restrict__ emb,
                                                  const float* __restrict__ mb,
                                                  int pass) {
    __shared__ float mbs[256][33];
    __shared__ float qs[32][33];
    int t = threadIdx.x;
    int m = blockIdx.x * 256 + t;
    int q0 = blockIdx.y * 32;
    int nq = (pass == 1) ? NQ1 : BSZ;

    float acc[32];
#pragma unroll
    for (int q = 0; q < 32; q++) acc[q] = 0.f;

    int dd = t & 31, rbase = t >> 5;
    for (int d0 = 0; d0 < DIM; d0 += 32) {
#pragma unroll
        for (int p = 0; p < 32; p++) {
            int r = rbase + p * 8;
            mbs[r][dd] = mb[(size_t)(blockIdx.x * 256 + r) * DIM + d0 + dd];
        }
#pragma unroll
        for (int p = 0; p < 4; p++) {
            int r = rbase + p * 8;
            int qi = q0 + r;
            float v = 0.f;
            if (qi < nq) {
                int gi = (pass == 1) ? g_cand[qi] : g_sel_nn[qi];
                const float* qsrc = (pass == 1) ? emb : mb;
                v = qsrc[(size_t)gi * DIM + d0 + dd];
            }
            qs[r][dd] = v;
        }
        __syncthreads();
#pragma unroll
        for (int d = 0; d < 32; d++) {
            float mv = mbs[t][d];
#pragma unroll
            for (int q = 0; q < 32; q++) acc[q] = fmaf(mv, qs[q][d], acc[q]);
        }
        __syncthreads();
    }

    float ym = g_y2[m];
#pragma unroll
    for (int q = 0; q < 32; q++) {
        int qi = q0 + q;
        if (qi < nq) {
            int gi = (pass == 1) ? g_cand[qi] : g_sel_nn[qi];
            float qn = (pass == 1) ? g_x2[gi] : g_y2[gi];
            g_d2q[(size_t)qi * M_BANK + m] = qn + ym - 2.f * acc[q];
        }
    }
}

// -------------------- 5) exact row min + patch selection -------------------
__global__ void rowmin_kernel() {
    __shared__ unsigned long long red[256];
    int qi = blockIdx.x, t = threadIdx.x;
    const float* row = g_d2q + (size_t)qi * M_BANK;
    unsigned long long best = ~0ull;
    for (int m = t; m < M_BANK; m += 256) {
        unsigned long long p = packmin(row[m], (unsigned)m);
        if (p < best) best = p;
    }
    red[t] = best;
    __syncthreads();
    for (int s = 128; s > 0; s >>= 1) {
        if (t < s && red[t + s] < red[t]) red[t] = red[t + s];
        __syncthreads();
    }
    if (t == 0) g_cpack[qi] = red[0];
}

__global__ void select_kernel() {
    int b = threadIdx.x;
    if (b >= BSZ) return;
    float bestd2 = -1e30f;
    int bestp = 0x7FFFFFFF, bestnn = 0;
    for (int j = 0; j < NCAND; j++) {
        int qi = b * NCAND + j;
        unsigned long long pk = g_cpack[qi];
        float d2 = unpackf(pk);
        int patch = g_cand[qi];
        if (d2 > bestd2 || (d2 == bestd2 && patch < bestp)) {
            bestd2 = d2;
            bestp = patch;
            bestnn = (int)(pk & 0xFFFFFFFFull);
        }
    }
    g_sel_patch[b] = bestp;
    g_sel_nn[b] = bestnn;
    g_sel_score[b] = sqrtf(fmaxf(bestd2, 0.f));
}

// ------------------------- 7) sorted top-9 supports ------------------------
__global__ void top9_kernel() {
    extern __shared__ unsigned long long sm9[];
    unsigned long long* arr = sm9;                 // M_BANK
    unsigned long long* red = sm9 + M_BANK;        // 256
    int b = blockIdx.x, t = threadIdx.x;
    const float* row = g_d2q + (size_t)b * M_BANK;
    for (int m = t; m < M_BANK; m += 256) arr[m] = packmin(row[m], (unsigned)m);
    __syncthreads();
    for (int it = 0; it < NSUP; it++) {
        unsigned long long best = ~0ull;
        for (int m = t; m < M_BANK; m += 256)
            if (arr[m] < best) best = arr[m];
        red[t] = best;
        __syncthreads();
        for (int s = 128; s > 0; s >>= 1) {
            if (t < s && red[t + s] < red[t]) red[t] = red[t + s];
            __syncthreads();
        }
        unsigned long long w = red[0];
        int m = (int)(w & 0xFFFFFFFFull);
        if (t == 0) {
            g_support[b * NSUP + it] = m;
            arr[m] = ~0ull;
        }
        __syncthreads();
    }
}

// ------------------------------ 8) final -----------------------------------
__global__ void final_kernel(const float* __restrict__ emb,
                             const float* __restrict__ mb,
                             float* __restrict__ out) {
    __shared__ float ds[NSUP];
    __shared__ float red[256];
    int b = blockIdx.x, t = threadIdx.x;
    const float* q = emb + (size_t)g_sel_patch[b] * DIM;
    for (int s = 0; s < NSUP; s++) {
        const float* sp = mb + (size_t)g_support[b * NSUP + s] * DIM;
        float ss = 0.f;
        for (int d = t; d < DIM; d += 256) {
            float df = q[d] - sp[d];
            ss += df * df;
        }
        red[t] = ss;
        __syncthreads();
        for (int st = 128; st > 0; st >>= 1) {
            if (t < st) red[t] += red[t + st];
            __syncthreads();
        }
        if (t == 0) ds[s] = sqrtf(fmaxf(red[0], 0.f));
        __syncthreads();
    }
    if (t == 0) {
        float mx = ds[0];
        for (int s = 1; s < NSUP; s++) mx = fmaxf(mx, ds[s]);
        float sum = 0.f, e0 = 0.f;
        for (int s = 0; s < NSUP; s++) {
            float e = expf(ds[s] - mx);
            sum += e;
            if (s == 0) e0 = e;
        }
        out[b] = (1.f - e0 / sum) * g_sel_score[b];
    }
}

// ------------------------------- launch ------------------------------------
extern "C" void kernel_launch(void* const* d_in, const int* in_sizes, int n_in,
                              void* d_out, int out_size) {
    const float* emb = (const float*)d_in[0];
    const float* mb = (const float*)d_in[1];
    float* out = (float*)d_out;

    cudaFuncSetAttribute(approx_kernel, cudaFuncAttributeMaxDynamicSharedMemorySize,
                         APPROX_SMEM);
    cudaFuncSetAttribute(top9_kernel, cudaFuncAttributeMaxDynamicSharedMemorySize,
                         TOP9_SMEM);

    prep_kernel<<<N_EMB + M_BANK, 128>>>(emb, mb);
    approx_kernel<<<dim3(N_EMB / BMa, MSPLIT), 256, APPROX_SMEM>>>();
    cand_kernel<<<BSZ, 256>>>();
    gemm_exact<<<dim3(M_BANK / 256, (NQ1 + 31) / 32), 256>>>(emb, mb, 1);
    rowmin_kernel<<<NQ1, 256>>>();
    select_kernel<<<1, 32>>>();
    gemm_exact<<<dim3(M_BANK / 256, 1), 256>>>(emb, mb, 2);
    top9_kernel<<<BSZ, 256, TOP9_SMEM>>>();
    final_kernel<<<BSZ, 256>>>(emb, mb, out);
}

// round 15
// speedup vs baseline: 1.1249x; 1.1249x over previous
#include <cuda_runtime.h>
#include <cuda_fp16.h>
#include <stdint.h>
#include <math.h>

// ---------------------------------------------------------------------------
// PatchCore pipeline (legacy-mma path; tcgen05 unavailable in this compile env):
//  1) prep: fp32 -> fp16 copies + row squared norms (x2, y2) + g_best init
//  2) approx: fp16 mma.sync (f16 accumulate) GEMM, 256x256 tile, ldmatrix
//     fragments, 3-stage cp.async pipeline, fused per-row running min of
//     (y2[m] - 2*dot) packed with index -> g_best[n]
//  3) cand: per image, top-NCAND patches by approx score (+ g_cpack init)
//  4) gemm_exact pass1: fp32 d2 for candidates, fused block-reduced rowmin
//     -> atomicMin g_cpack (no d2 materialization)
//  5) select: exact argmax patch, exact nn index, exact score
//  6) gemm_exact pass2: fp32 d2 rows for the 16 nn samples -> g_d2q
//  7) top9: exact sorted 9 nearest supports
//  8) final: distances, softmax, output
// ---------------------------------------------------------------------------

#define N_EMB 12544
#define M_BANK 16384
#define DIM 1536
#define BSZ 16
#define PPI (N_EMB / BSZ)        // 784
#define NCAND 8
#define NQ1 (BSZ * NCAND)        // 128
#define NSUP 9

#define BMa 256
#define BNa 256
#define BKa 32
#define PK 40                    // padded row stride (fp16) -> LDSM conflict-free
#define NKT (DIM / BKa)          // 48
#define NCHUNK (M_BANK / BNa)    // 64
#define MSPLIT 3
#define NSTAGE 3
#define STAGE_ELEMS ((BMa + BNa) * PK)                           // 20480

#define APPROX_SMEM (NSTAGE * STAGE_ELEMS * 2 + 256 * 8)        // 124928 B
#define TOP9_SMEM ((M_BANK + 256) * 8)                           // 133120 B

// ------------------------- device scratch (static) -------------------------
__device__ __half g_emb_h[(size_t)N_EMB * DIM];
__device__ __half g_mb_h[(size_t)M_BANK * DIM];
__device__ float g_x2[N_EMB];
__device__ float g_y2[M_BANK];
__device__ unsigned long long g_best[N_EMB];
__device__ int g_cand[NQ1];
__device__ float g_d2q[(size_t)BSZ * M_BANK];
__device__ unsigned long long g_cpack[NQ1];
__device__ int g_sel_patch[BSZ];
__device__ int g_sel_nn[BSZ];
__device__ float g_sel_score[BSZ];
__device__ int g_support[BSZ * NSUP];

// ------------------------------- helpers -----------------------------------
__device__ __forceinline__ unsigned int fflip(float f) {
    unsigned int u = __float_as_uint(f);
    return (u & 0x80000000u) ? ~u : (u | 0x80000000u);
}
__device__ __forceinline__ float funflip(unsigned int u) {
    u = (u & 0x80000000u) ? (u & 0x7FFFFFFFu) : ~u;
    return __uint_as_float(u);
}
__device__ __forceinline__ unsigned long long packmin(float f, unsigned int idx) {
    return ((unsigned long long)fflip(f) << 32) | (unsigned long long)idx;
}
__device__ __forceinline__ float unpackf(unsigned long long p) {
    return funflip((unsigned int)(p >> 32));
}

__device__ __forceinline__ void cpasync16(uint32_t saddr, const void* gptr) {
    asm volatile("cp.async.cg.shared.global [%0], [%1], 16;\n" :: "r"(saddr), "l"(gptr));
}
__device__ __forceinline__ void cp_commit() {
    asm volatile("cp.async.commit_group;\n" ::: "memory");
}
__device__ __forceinline__ void cp_wait1() {
    asm volatile("cp.async.wait_group 1;\n" ::: "memory");
}
__device__ __forceinline__ void cp_wait0() {
    asm volatile("cp.async.wait_group 0;\n" ::: "memory");
}

__device__ __forceinline__ void ldsm_x4(uint32_t* r, uint32_t addr) {
    asm volatile("ldmatrix.sync.aligned.m8n8.x4.shared.b16 {%0,%1,%2,%3}, [%4];\n"
                 : "=r"(r[0]), "=r"(r[1]), "=r"(r[2]), "=r"(r[3]) : "r"(addr));
}

// fp16 x fp16 -> fp16 accumulate
__device__ __forceinline__ void mma16816h(uint32_t* c, const uint32_t* a,
                                          uint32_t b0, uint32_t b1) {
    asm volatile(
        "mma.sync.aligned.m16n8k16.row.col.f16.f16.f16.f16 "
        "{%0,%1}, {%2,%3,%4,%5}, {%6,%7}, {%0,%1};\n"
        : "+r"(c[0]), "+r"(c[1])
        : "r"(a[0]), "r"(a[1]), "r"(a[2]), "r"(a[3]), "r"(b0), "r"(b1));
}

// ------------------------------ 1) prep ------------------------------------
__global__ void __launch_bounds__(128) prep_kernel(const float* __restrict__ emb,
                                                   const float* __restrict__ mb) {
    __shared__ float wred[4];
    int row = blockIdx.x;
    const float* src;
    __half* dst;
    float* normp;
    if (row < N_EMB) {
        src = emb + (size_t)row * DIM;
        dst = g_emb_h + (size_t)row * DIM;
        normp = &g_x2[row];
        if (threadIdx.x == 0) g_best[row] = ~0ull;
    } else {
        int r = row - N_EMB;
        src = mb + (size_t)r * DIM;
        dst = g_mb_h + (size_t)r * DIM;
        normp = &g_y2[r];
    }
    int t = threadIdx.x;
    float ss = 0.f;
    const float4* s4 = (const float4*)src;
#pragma unroll
    for (int i = 0; i < DIM / 4 / 128; i++) {
        int c = t + i * 128;
        float4 v = s4[c];
        ss = fmaf(v.x, v.x, ss);
        ss = fmaf(v.y, v.y, ss);
        ss = fmaf(v.z, v.z, ss);
        ss = fmaf(v.w, v.w, ss);
        __half2* d2 = (__half2*)(dst + c * 4);
        d2[0] = __floats2half2_rn(v.x, v.y);
        d2[1] = __floats2half2_rn(v.z, v.w);
    }
#pragma unroll
    for (int s = 16; s > 0; s >>= 1) ss += __shfl_xor_sync(0xFFFFFFFFu, ss, s);
    if ((t & 31) == 0) wred[t >> 5] = ss;
    __syncthreads();
    if (t == 0) *normp = wred[0] + wred[1] + wred[2] + wred[3];
}

// ------------------------- 2) approx fp16 GEMM+min -------------------------
__device__ __forceinline__ void load_tiles(int t, int row0, int m0, int stage, int kt,
                                           uint32_t sbase) {
    int k0 = kt * BKa;
    uint32_t abase = sbase + (uint32_t)(stage * STAGE_ELEMS) * 2u;
    uint32_t bbase = abase + (uint32_t)(BMa * PK) * 2u;
#pragma unroll
    for (int i = 0; i < 4; i++) {           // A: 256 rows x 32 k = 1024 x 16B
        int c = t + i * 256;
        int r = c >> 2, cc = c & 3;
        cpasync16(abase + (uint32_t)(r * PK + cc * 8) * 2u,
                  g_emb_h + (size_t)(row0 + r) * DIM + k0 + cc * 8);
    }
#pragma unroll
    for (int i = 0; i < 4; i++) {           // B: 256 rows x 32 k = 1024 x 16B
        int c = t + i * 256;
        int r = c >> 2, cc = c & 3;
        cpasync16(bbase + (uint32_t)(r * PK + cc * 8) * 2u,
                  g_mb_h + (size_t)(m0 + r) * DIM + k0 + cc * 8);
    }
}

extern "C" __global__ void __launch_bounds__(256, 1) approx_kernel() {
    extern __shared__ char smem[];
    unsigned long long* rowmin =
        (unsigned long long*)(smem + NSTAGE * STAGE_ELEMS * 2);

    int t = threadIdx.x;
    rowmin[t] = ~0ull;
    __syncthreads();

    int lane = t & 31, wid = t >> 5;
    int wr = wid >> 1, wc = wid & 1;   // 4x2 warps, each a 64x128 tile
    int g = lane >> 2, tq = lane & 3;
    int row0 = blockIdx.x * BMa;

    uint32_t sbase = (uint32_t)__cvta_generic_to_shared(smem);

    uint32_t a_off[4];
#pragma unroll
    for (int i = 0; i < 4; i++)
        a_off[i] = (uint32_t)((wr * 64 + i * 16 + (lane & 15)) * PK +
                              ((lane >> 4) & 1) * 8) * 2u;
    uint32_t b_off[16];
#pragma unroll
    for (int j = 0; j < 16; j++)
        b_off[j] = (uint32_t)((wc * 128 + j * 8 + (lane & 7)) * PK +
                              (lane >> 3) * 8) * 2u;

    unsigned long long slot[8];
#pragma unroll
    for (int i = 0; i < 8; i++) slot[i] = ~0ull;

    for (int chunk = blockIdx.y; chunk < NCHUNK; chunk += MSPLIT) {
        int m0 = chunk * BNa;
        uint32_t acc[4][16][2];            // f16x2 accumulators (64x128 per warp)
#pragma unroll
        for (int i = 0; i < 4; i++)
#pragma unroll
            for (int j = 0; j < 16; j++) { acc[i][j][0] = 0u; acc[i][j][1] = 0u; }

        __syncthreads();
        load_tiles(t, row0, m0, 0, 0, sbase);
        cp_commit();
        load_tiles(t, row0, m0, 1, 1, sbase);
        cp_commit();

        for (int kt = 0; kt < NKT; kt++) {
            if (kt + 1 < NKT) cp_wait1(); else cp_wait0();
            __syncthreads();
            if (kt + 2 < NKT) {
                load_tiles(t, row0, m0, (kt + 2) % NSTAGE, kt + 2, sbase);
                cp_commit();
            }

            int stage = kt % NSTAGE;
            uint32_t abase = sbase + (uint32_t)(stage * STAGE_ELEMS) * 2u;
            uint32_t bbase = abase + (uint32_t)(BMa * PK) * 2u;

            // j-halves keep only 8 B-fragments live at a time
#pragma unroll
            for (int jh = 0; jh < 2; jh++) {
                uint32_t bf[8][4];
#pragma unroll
                for (int jj = 0; jj < 8; jj++)
                    ldsm_x4(bf[jj], bbase + b_off[jh * 8 + jj]);
#pragma unroll
                for (int kk2 = 0; kk2 < 2; kk2++) {
                    uint32_t af[4][4];
#pragma unroll
                    for (int i = 0; i < 4; i++)
                        ldsm_x4(af[i], abase + a_off[i] + (uint32_t)(kk2 * 16 * 2));
#pragma unroll
                    for (int jj = 0; jj < 8; jj++)
#pragma unroll
                        for (int i = 0; i < 4; i++)
                            mma16816h(acc[i][jh * 8 + jj], af[i],
                                      bf[jj][kk2 * 2], bf[jj][kk2 * 2 + 1]);
                }
            }
        }

        // epilogue: c0 = row g, c1 = row g+8; halves = cols tq*2, tq*2+1
#pragma unroll
        for (int j = 0; j < 16; j++) {
            int m = m0 + wc * 128 + j * 8 + tq * 2;
            float y0 = __ldg(&g_y2[m]);
            float y1 = __ldg(&g_y2[m + 1]);
#pragma unroll
            for (int i = 0; i < 4; i++) {
                float2 f0 = __half22float2(*(__half2*)&acc[i][j][0]);
                float2 f1 = __half22float2(*(__half2*)&acc[i][j][1]);
                unsigned long long p;
                p = packmin(fmaf(-2.f, f0.x, y0), (unsigned)m);
                if (p < slot[i * 2]) slot[i * 2] = p;
                p = packmin(fmaf(-2.f, f0.y, y1), (unsigned)(m + 1));
                if (p < slot[i * 2]) slot[i * 2] = p;
                p = packmin(fmaf(-2.f, f1.x, y0), (unsigned)m);
                if (p < slot[i * 2 + 1]) slot[i * 2 + 1] = p;
                p = packmin(fmaf(-2.f, f1.y, y1), (unsigned)(m + 1));
                if (p < slot[i * 2 + 1]) slot[i * 2 + 1] = p;
            }
        }
    }

#pragma unroll
    for (int i = 0; i < 4; i++) {
        atomicMin(&rowmin[wr * 64 + i * 16 + g], slot[i * 2]);
        atomicMin(&rowmin[wr * 64 + i * 16 + g + 8], slot[i * 2 + 1]);
    }
    __syncthreads();
    atomicMin(&g_best[row0 + t], rowmin[t]);
}

// -------------------- 3) candidate patches per image -----------------------
__global__ void cand_kernel() {
    __shared__ unsigned long long sarr[PPI];
    __shared__ unsigned long long red[256];
    int b = blockIdx.x, t = threadIdx.x;
    if (b == 0 && t < NQ1) g_cpack[t] = ~0ull;     // init for pass1 atomicMin
    for (int p = t; p < PPI; p += 256) {
        int n = b * PPI + p;
        float sc = g_x2[n] + unpackf(g_best[n]);
        sarr[p] = ((unsigned long long)fflip(sc) << 32) |
                  (unsigned long long)(0xFFFFFFFFu - (unsigned)p);
    }
    __syncthreads();
    for (int it = 0; it < NCAND; it++) {
        unsigned long long mx = 0ull;
        for (int p = t; p < PPI; p += 256) mx = (sarr[p] > mx) ? sarr[p] : mx;
        red[t] = mx;
        __syncthreads();
        for (int s = 128; s > 0; s >>= 1) {
            if (t < s && red[t + s] > red[t]) red[t] = red[t + s];
            __syncthreads();
        }
        unsigned long long w = red[0];
        int p = (int)(0xFFFFFFFFu - (unsigned)(w & 0xFFFFFFFFull));
        if (t == 0) {
            g_cand[b * NCAND + it] = b * PPI + p;
            sarr[p] = 0ull;
        }
        __syncthreads();
    }
}

// ---------------- 4/6) exact fp32 d2 for query sets ------------------------
// pass==1: NQ1 candidate rows, fused rowmin -> g_cpack (no d2 writes)
// pass==2: BSZ nn rows, d2 rows -> g_d2q
__global__ void __launch_bounds__(256) gemm_exact(const float* __restrict__ emb,
                                                  const float* __restrict__ mb,
                                                  int pass) {
    __shared__ float mbs[256][36];
    __shared__ float qs[32][36];
    __shared__ unsigned long long wred[32][8];
    int t = threadIdx.x;
    int m = blockIdx.x * 256 + t;
    int q0 = blockIdx.y * 32;
    int nq = (pass == 1) ? NQ1 : BSZ;

    float acc[32];
#pragma unroll
    for (int q = 0; q < 32; q++) acc[q] = 0.f;

    int dd = t & 31, rbase = t >> 5;
    for (int d0 = 0; d0 < DIM; d0 += 32) {
#pragma unroll
        for (int p = 0; p < 32; p++) {
            int r = rbase + p * 8;
            mbs[r][dd] = mb[(size_t)(blockIdx.x * 256 + r) * DIM + d0 + dd];
        }
#pragma unroll
        for (int p = 0; p < 4; p++) {
            int r = rbase + p * 8;
            int qi = q0 + r;
            float v = 0.f;
            if (qi < nq) {
                int gi = (pass == 1) ? g_cand[qi] : g_sel_nn[qi];
                const float* qsrc = (pass == 1) ? emb : mb;
                v = qsrc[(size_t)gi * DIM + d0 + dd];
            }
            qs[r][dd] = v;
        }
        __syncthreads();
#pragma unroll
        for (int dg = 0; dg < 8; dg++) {
            float4 mv = *(const float4*)&mbs[t][dg * 4];
#pragma unroll
            for (int q = 0; q < 32; q++) {
                float4 qv = *(const float4*)&qs[q][dg * 4];
                acc[q] = fmaf(mv.x, qv.x, acc[q]);
                acc[q] = fmaf(mv.y, qv.y, acc[q]);
                acc[q] = fmaf(mv.z, qv.z, acc[q]);
                acc[q] = fmaf(mv.w, qv.w, acc[q]);
            }
        }
        __syncthreads();
    }

    float ym = g_y2[m];
    if (pass == 1) {
        int lane = t & 31, w = t >> 5;
#pragma unroll
        for (int q = 0; q < 32; q++) {
            int qi = q0 + q;
            int gi = g_cand[qi];
            float d2 = g_x2[gi] + ym - 2.f * acc[q];
            unsigned long long p = packmin(d2, (unsigned)m);
#pragma unroll
            for (int s = 16; s > 0; s >>= 1) {
                unsigned long long o = __shfl_xor_sync(0xFFFFFFFFu, p, s);
                if (o < p) p = o;
            }
            if (lane == 0) wred[q][w] = p;
        }
        __syncthreads();
        // 256 threads = 32 q x 8 warp-partials; groups of 8 within a warp
        unsigned long long p = wred[t >> 3][t & 7];
#pragma unroll
        for (int s = 4; s > 0; s >>= 1) {
            unsigned long long o = __shfl_xor_sync(0xFFFFFFFFu, p, s);
            if (o < p) p = o;
        }
        if ((t & 7) == 0) atomicMin(&g_cpack[q0 + (t >> 3)], p);
    } else {
#pragma unroll
        for (int q = 0; q < 32; q++) {
            int qi = q0 + q;
            if (qi < nq) {
                int gi = g_sel_nn[qi];
                g_d2q[(size_t)qi * M_BANK + m] = g_y2[gi] + ym - 2.f * acc[q];
            }
        }
    }
}

// -------------------- 5) exact patch selection -----------------------------
__global__ void select_kernel() {
    int b = threadIdx.x;
    if (b >= BSZ) return;
    float bestd2 = -1e30f;
    int bestp = 0x7FFFFFFF, bestnn = 0;
    for (int j = 0; j < NCAND; j++) {
        int qi = b * NCAND + j;
        unsigned long long pk = g_cpack[qi];
        float d2 = unpackf(pk);
        int patch = g_cand[qi];
        if (d2 > bestd2 || (d2 == bestd2 && patch < bestp)) {
            bestd2 = d2;
            bestp = patch;
            bestnn = (int)(pk & 0xFFFFFFFFull);
        }
    }
    g_sel_patch[b] = bestp;
    g_sel_nn[b] = bestnn;
    g_sel_score[b] = sqrtf(fmaxf(bestd2, 0.f));
}

// ------------------------- 7) sorted top-9 supports ------------------------
__global__ void top9_kernel() {
    extern __shared__ unsigned long long sm9[];
    unsigned long long* arr = sm9;
    unsigned long long* red = sm9 + M_BANK;
    int b = blockIdx.x, t = threadIdx.x;
    const float* row = g_d2q + (size_t)b * M_BANK;
    for (int m = t; m < M_BANK; m += 256) arr[m] = packmin(row[m], (unsigned)m);
    __syncthreads();
    for (int it = 0; it < NSUP; it++) {
        unsigned long long best = ~0ull;
        for (int m = t; m < M_BANK; m += 256)
            if (arr[m] < best) best = arr[m];
        red[t] = best;
        __syncthreads();
        for (int s = 128; s > 0; s >>= 1) {
            if (t < s && red[t + s] < red[t]) red[t] = red[t + s];
            __syncthreads();
        }
        unsigned long long w = red[0];
        int m = (int)(w & 0xFFFFFFFFull);
        if (t == 0) {
            g_support[b * NSUP + it] = m;
            arr[m] = ~0ull;
        }
        __syncthreads();
    }
}

// ------------------------------ 8) final -----------------------------------
__global__ void final_kernel(const float* __restrict__ emb,
                             const float* __restrict__ mb,
                             float* __restrict__ out) {
    __shared__ float ds[NSUP];
    __shared__ float red[256];
    int b = blockIdx.x, t = threadIdx.x;
    const float* q = emb + (size_t)g_sel_patch[b] * DIM;
    for (int s = 0; s < NSUP; s++) {
        const float* sp = mb + (size_t)g_support[b * NSUP + s] * DIM;
        float ss = 0.f;
        for (int d = t; d < DIM; d += 256) {
            float df = q[d] - sp[d];
            ss += df * df;
        }
        red[t] = ss;
        __syncthreads();
        for (int st = 128; st > 0; st >>= 1) {
            if (t < st) red[t] += red[t + st];
            __syncthreads();
        }
        if (t == 0) ds[s] = sqrtf(fmaxf(red[0], 0.f));
        __syncthreads();
    }
    if (t == 0) {
        float mx = ds[0];
        for (int s = 1; s < NSUP; s++) mx = fmaxf(mx, ds[s]);
        float sum = 0.f, e0 = 0.f;
        for (int s = 0; s < NSUP; s++) {
            float e = expf(ds[s] - mx);
            sum += e;
            if (s == 0) e0 = e;
        }
        out[b] = (1.f - e0 / sum) * g_sel_score[b];
    }
}

// ------------------------------- launch ------------------------------------
extern "C" void kernel_launch(void* const* d_in, const int* in_sizes, int n_in,
                              void* d_out, int out_size) {
    const float* emb = (const float*)d_in[0];
    const float* mb = (const float*)d_in[1];
    float* out = (float*)d_out;

    cudaFuncSetAttribute(approx_kernel, cudaFuncAttributeMaxDynamicSharedMemorySize,
                         APPROX_SMEM);
    cudaFuncSetAttribute(top9_kernel, cudaFuncAttributeMaxDynamicSharedMemorySize,
                         TOP9_SMEM);

    prep_kernel<<<N_EMB + M_BANK, 128>>>(emb, mb);
    approx_kernel<<<dim3(N_EMB / BMa, MSPLIT), 256, APPROX_SMEM>>>();
    cand_kernel<<<BSZ, 256>>>();
    gemm_exact<<<dim3(M_BANK / 256, NQ1 / 32), 256>>>(emb, mb, 1);
    select_kernel<<<1, 32>>>();
    gemm_exact<<<dim3(M_BANK / 256, 1), 256>>>(emb, mb, 2);
    top9_kernel<<<BSZ, 256, TOP9_SMEM>>>();
    final_kernel<<<BSZ, 256>>>(emb, mb, out);
}